// round 1
// baseline (speedup 1.0000x reference)
#include <cuda_runtime.h>
#include <cuda_bf16.h>
#include <cstdint>

// ---------------------------------------------------------------------------
// Problem constants (fixed by setup_inputs)
// ---------------------------------------------------------------------------
#define NBATCH 4
#define LQ     8192
#define NQ     (NBATCH * LQ)        // 32768
#define DMODEL 256
#define NHEAD  8
#define HDIM   32
#define NLVL   4
#define NPNT   4
#define LIN    21760                // 128^2 + 64^2 + 32^2 + 16^2
#define NV     (NBATCH * LIN)       // 87040
#define DFF    1024

// ---------------------------------------------------------------------------
// Device scratch (static allocation — no cudaMalloc allowed)
// ---------------------------------------------------------------------------
__device__ float g_q    [(size_t)NQ * DMODEL];
__device__ float g_value[(size_t)NV * DMODEL];
__device__ float g_off  [(size_t)NQ * DMODEL];       // 256 = NH*NL*NP*2
__device__ float g_aw   [(size_t)NQ * NHEAD * 16];
__device__ float g_attn [(size_t)NQ * DMODEL];
__device__ float g_proj [(size_t)NQ * DMODEL];
__device__ float g_x    [(size_t)NQ * DMODEL];
__device__ float g_h    [(size_t)NQ * DFF];

// ---------------------------------------------------------------------------
// Elementwise add (q = tgt + query_pos), float4-vectorized
// ---------------------------------------------------------------------------
__global__ void add2_kernel(const float* __restrict__ a, const float* __restrict__ b,
                            float* __restrict__ c, int n4) {
    int i = blockIdx.x * blockDim.x + threadIdx.x;
    if (i >= n4) return;
    float4 va = reinterpret_cast<const float4*>(a)[i];
    float4 vb = reinterpret_cast<const float4*>(b)[i];
    float4 vc;
    vc.x = va.x + vb.x; vc.y = va.y + vb.y; vc.z = va.z + vb.z; vc.w = va.w + vb.w;
    reinterpret_cast<float4*>(c)[i] = vc;
}

// ---------------------------------------------------------------------------
// SGEMM: C[M,N] = A[M,K] @ B[K,N] + bias[N]  (optional ReLU)
// 128x128 block tile, 8x8 per thread, BK=8, 256 threads.
// Requires M%128==0, N%128==0, K%8==0 (all shapes here satisfy this).
// ---------------------------------------------------------------------------
template <bool RELU>
__global__ __launch_bounds__(256)
void sgemm_bias_kernel(int M, int N, int K,
                       const float* __restrict__ A, const float* __restrict__ B,
                       const float* __restrict__ bias, float* __restrict__ C) {
    constexpr int BM = 128, BN = 128, BK = 8, TM = 8, TN = 8;
    __shared__ float As[BK][BM];
    __shared__ float Bs[BK][BN];

    const int tid  = threadIdx.x;
    const int trow = tid / 16;          // 0..15
    const int tcol = tid % 16;          // 0..15
    const int row0 = blockIdx.y * BM;
    const int col0 = blockIdx.x * BN;

    const int a_row = tid >> 1;         // 0..127
    const int a_col = (tid & 1) * 4;    // 0 or 4
    const int b_row = tid >> 5;         // 0..7
    const int b_col = (tid & 31) * 4;   // 0..124

    float acc[TM][TN];
#pragma unroll
    for (int i = 0; i < TM; i++)
#pragma unroll
        for (int j = 0; j < TN; j++) acc[i][j] = 0.f;

    const float* Ab = A + (size_t)(row0 + a_row) * K;
    for (int k0 = 0; k0 < K; k0 += BK) {
        float4 av = *reinterpret_cast<const float4*>(Ab + k0 + a_col);
        As[a_col + 0][a_row] = av.x;
        As[a_col + 1][a_row] = av.y;
        As[a_col + 2][a_row] = av.z;
        As[a_col + 3][a_row] = av.w;
        *reinterpret_cast<float4*>(&Bs[b_row][b_col]) =
            *reinterpret_cast<const float4*>(B + (size_t)(k0 + b_row) * N + col0 + b_col);
        __syncthreads();
#pragma unroll
        for (int k = 0; k < BK; k++) {
            float ar[TM], br[TN];
#pragma unroll
            for (int i = 0; i < TM; i++) ar[i] = As[k][trow * TM + i];
#pragma unroll
            for (int j = 0; j < TN; j++) br[j] = Bs[k][tcol * TN + j];
#pragma unroll
            for (int i = 0; i < TM; i++)
#pragma unroll
                for (int j = 0; j < TN; j++) acc[i][j] = fmaf(ar[i], br[j], acc[i][j]);
        }
        __syncthreads();
    }

#pragma unroll
    for (int i = 0; i < TM; i++) {
        const int r = row0 + trow * TM + i;
#pragma unroll
        for (int j = 0; j < TN; j += 4) {
            const int c = col0 + tcol * TN + j;
            float4 v;
            v.x = acc[i][j + 0] + bias[c + 0];
            v.y = acc[i][j + 1] + bias[c + 1];
            v.z = acc[i][j + 2] + bias[c + 2];
            v.w = acc[i][j + 3] + bias[c + 3];
            if (RELU) {
                v.x = fmaxf(v.x, 0.f); v.y = fmaxf(v.y, 0.f);
                v.z = fmaxf(v.z, 0.f); v.w = fmaxf(v.w, 0.f);
            }
            *reinterpret_cast<float4*>(C + (size_t)r * N + c) = v;
        }
    }
}

// ---------------------------------------------------------------------------
// Zero masked value rows (mask is all-false in this dataset, but stay faithful)
// ---------------------------------------------------------------------------
__global__ void mask_zero_kernel(const unsigned char* __restrict__ mask,
                                 float* __restrict__ value) {
    int row  = blockIdx.x * 8 + (threadIdx.x >> 5);
    int lane = threadIdx.x & 31;
    if (row >= NV) return;
    if (mask[row]) {
        float* v = value + (size_t)row * DMODEL;
        for (int c = lane; c < DMODEL; c += 32) v[c] = 0.f;
    }
}

// ---------------------------------------------------------------------------
// Softmax over the 16 (level,point) logits per (query, head)
// ---------------------------------------------------------------------------
__global__ void softmax16_kernel(float* __restrict__ aw) {
    int idx = blockIdx.x * blockDim.x + threadIdx.x;   // (nq*NHEAD)
    if (idx >= NQ * NHEAD) return;
    float* a = aw + (size_t)idx * 16;
    float v[16];
    float m = -1e30f;
#pragma unroll
    for (int i = 0; i < 16; i++) { v[i] = a[i]; m = fmaxf(m, v[i]); }
    float s = 0.f;
#pragma unroll
    for (int i = 0; i < 16; i++) { v[i] = expf(v[i] - m); s += v[i]; }
    float inv = 1.f / s;
#pragma unroll
    for (int i = 0; i < 16; i++) a[i] = v[i] * inv;
}

// ---------------------------------------------------------------------------
// Deformable bilinear sampling + weighted sum.
// One warp per (n, q, head); lane = channel within the 32-wide head slice.
// Each corner load is a fully-coalesced 128B line.
// ---------------------------------------------------------------------------
__global__ __launch_bounds__(256)
void deform_sample_kernel(const float* __restrict__ value,
                          const float* __restrict__ off,
                          const float* __restrict__ aw,
                          const float* __restrict__ refp,
                          float* __restrict__ out) {
    const int gw   = (blockIdx.x * blockDim.x + threadIdx.x) >> 5;
    const int lane = threadIdx.x & 31;
    if (gw >= NQ * NHEAD) return;
    const int h  = gw & (NHEAD - 1);
    const int nq = gw >> 3;
    const int n  = nq / LQ;

    const int   HW[4]  = {128, 64, 32, 16};
    const int   LST[4] = {0, 16384, 20480, 21504};

    const float* offr  = off  + (size_t)nq * (NHEAD * NLVL * NPNT * 2) + h * (NLVL * NPNT * 2);
    const float* awr   = aw   + (size_t)nq * (NHEAD * 16) + h * 16;
    const float* refr  = refp + (size_t)nq * (NLVL * 2);
    const float* vbase = value + (size_t)n * LIN * DMODEL + h * HDIM + lane;

    float acc = 0.f;
#pragma unroll
    for (int l = 0; l < NLVL; l++) {
        const int   Hl = HW[l];
        const float rx = refr[l * 2 + 0] * (float)Hl - 0.5f;  // square levels: W==H
        const float ry = refr[l * 2 + 1] * (float)Hl - 0.5f;
        const float* vl = vbase + (size_t)LST[l] * DMODEL;
#pragma unroll
        for (int p = 0; p < NPNT; p++) {
            const float px = rx + offr[(l * NPNT + p) * 2 + 0];
            const float py = ry + offr[(l * NPNT + p) * 2 + 1];
            const float w  = awr[l * NPNT + p];
            const float x0f = floorf(px), y0f = floorf(py);
            const float dx = px - x0f, dy = py - y0f;
            const int x0 = (int)x0f, y0 = (int)y0f;
            const float cw[4] = {(1.f - dx) * (1.f - dy), dx * (1.f - dy),
                                 (1.f - dx) * dy,         dx * dy};
            const int cx[4] = {x0, x0 + 1, x0, x0 + 1};
            const int cy[4] = {y0, y0, y0 + 1, y0 + 1};
#pragma unroll
            for (int c = 0; c < 4; c++) {
                if (cx[c] >= 0 && cx[c] < Hl && cy[c] >= 0 && cy[c] < Hl) {
                    acc = fmaf(w * cw[c], vl[(size_t)(cy[c] * Hl + cx[c]) * DMODEL], acc);
                }
            }
        }
    }
    out[(size_t)nq * DMODEL + h * HDIM + lane] = acc;
}

// ---------------------------------------------------------------------------
// Fused residual add + LayerNorm over D=256. One warp per row (8 elems/lane).
// ---------------------------------------------------------------------------
__global__ __launch_bounds__(256)
void add_ln_kernel(const float* __restrict__ a, const float* __restrict__ b,
                   const float* __restrict__ g, const float* __restrict__ beta,
                   float* __restrict__ out) {
    const int row  = blockIdx.x * 8 + (threadIdx.x >> 5);
    const int lane = threadIdx.x & 31;
    if (row >= NQ) return;
    const float4* ar = reinterpret_cast<const float4*>(a + (size_t)row * DMODEL);
    const float4* br = reinterpret_cast<const float4*>(b + (size_t)row * DMODEL);

    float xv[8];
    float s = 0.f, s2 = 0.f;
#pragma unroll
    for (int t = 0; t < 2; t++) {
        float4 u = ar[lane + t * 32];
        float4 w = br[lane + t * 32];
        xv[t * 4 + 0] = u.x + w.x;
        xv[t * 4 + 1] = u.y + w.y;
        xv[t * 4 + 2] = u.z + w.z;
        xv[t * 4 + 3] = u.w + w.w;
#pragma unroll
        for (int j = 0; j < 4; j++) {
            float v = xv[t * 4 + j];
            s += v; s2 = fmaf(v, v, s2);
        }
    }
#pragma unroll
    for (int o = 16; o > 0; o >>= 1) {
        s  += __shfl_xor_sync(0xFFFFFFFFu, s, o);
        s2 += __shfl_xor_sync(0xFFFFFFFFu, s2, o);
    }
    const float mean = s * (1.f / DMODEL);
    const float var  = s2 * (1.f / DMODEL) - mean * mean;
    const float inv  = rsqrtf(var + 1e-5f);

    float4* orow = reinterpret_cast<float4*>(out + (size_t)row * DMODEL);
    const float4* gr = reinterpret_cast<const float4*>(g);
    const float4* be = reinterpret_cast<const float4*>(beta);
#pragma unroll
    for (int t = 0; t < 2; t++) {
        float4 gv = gr[lane + t * 32];
        float4 bv = be[lane + t * 32];
        float4 ov;
        ov.x = (xv[t * 4 + 0] - mean) * inv * gv.x + bv.x;
        ov.y = (xv[t * 4 + 1] - mean) * inv * gv.y + bv.y;
        ov.z = (xv[t * 4 + 2] - mean) * inv * gv.z + bv.z;
        ov.w = (xv[t * 4 + 3] - mean) * inv * gv.w + bv.w;
        orow[lane + t * 32] = ov;
    }
}

// ---------------------------------------------------------------------------
// kernel_launch
// ---------------------------------------------------------------------------
extern "C" void kernel_launch(void* const* d_in, const int* in_sizes, int n_in,
                              void* d_out, int out_size) {
    const float*         tgt    = (const float*)d_in[0];
    const float*         qpos   = (const float*)d_in[1];
    const float*         refp   = (const float*)d_in[2];
    const float*         src    = (const float*)d_in[3];
    // d_in[4] = src_spatial_shapes (int64), d_in[5] = level_start_index (int64) — constants, hardcoded
    const unsigned char* mask   = (const unsigned char*)d_in[6];
    const float*         W_off  = (const float*)d_in[7];
    const float*         b_off  = (const float*)d_in[8];
    const float*         W_attn = (const float*)d_in[9];
    const float*         b_attn = (const float*)d_in[10];
    const float*         W_val  = (const float*)d_in[11];
    const float*         b_val  = (const float*)d_in[12];
    const float*         W_out  = (const float*)d_in[13];
    const float*         b_out  = (const float*)d_in[14];
    const float*         ln1g   = (const float*)d_in[15];
    const float*         ln1b   = (const float*)d_in[16];
    const float*         W_fc1  = (const float*)d_in[17];
    const float*         b_fc1  = (const float*)d_in[18];
    const float*         W_fc2  = (const float*)d_in[19];
    const float*         b_fc2  = (const float*)d_in[20];
    const float*         ln2g   = (const float*)d_in[21];
    const float*         ln2b   = (const float*)d_in[22];
    float*               out    = (float*)d_out;

    float *q_p, *value_p, *off_p, *aw_p, *attn_p, *proj_p, *x_p, *h_p;
    cudaGetSymbolAddress((void**)&q_p,     g_q);
    cudaGetSymbolAddress((void**)&value_p, g_value);
    cudaGetSymbolAddress((void**)&off_p,   g_off);
    cudaGetSymbolAddress((void**)&aw_p,    g_aw);
    cudaGetSymbolAddress((void**)&attn_p,  g_attn);
    cudaGetSymbolAddress((void**)&proj_p,  g_proj);
    cudaGetSymbolAddress((void**)&x_p,     g_x);
    cudaGetSymbolAddress((void**)&h_p,     g_h);

    // 1. q = tgt + query_pos
    {
        int n4 = NQ * DMODEL / 4;
        add2_kernel<<<(n4 + 255) / 256, 256>>>(tgt, qpos, q_p, n4);
    }
    // 2. value = src @ W_val + b_val, then mask
    sgemm_bias_kernel<false><<<dim3(DMODEL / 128, NV / 128), 256>>>(
        NV, DMODEL, DMODEL, src, W_val, b_val, value_p);
    mask_zero_kernel<<<(NV + 7) / 8, 256>>>(mask, value_p);
    // 3. offsets = q @ W_off + b_off
    sgemm_bias_kernel<false><<<dim3(DMODEL / 128, NQ / 128), 256>>>(
        NQ, DMODEL, DMODEL, q_p, W_off, b_off, off_p);
    // 4. attn logits = q @ W_attn + b_attn; softmax over 16
    sgemm_bias_kernel<false><<<dim3(128 / 128, NQ / 128), 256>>>(
        NQ, 128, DMODEL, q_p, W_attn, b_attn, aw_p);
    softmax16_kernel<<<(NQ * NHEAD + 255) / 256, 256>>>(aw_p);
    // 5. deformable sampling
    deform_sample_kernel<<<NQ * NHEAD / 8, 256>>>(value_p, off_p, aw_p, refp, attn_p);
    // 6. out projection
    sgemm_bias_kernel<false><<<dim3(DMODEL / 128, NQ / 128), 256>>>(
        NQ, DMODEL, DMODEL, attn_p, W_out, b_out, proj_p);
    // 7. x = LN(tgt + attn_out)
    add_ln_kernel<<<NQ / 8, 256>>>(tgt, proj_p, ln1g, ln1b, x_p);
    // 8. h = relu(x @ W_fc1 + b_fc1)
    sgemm_bias_kernel<true><<<dim3(DFF / 128, NQ / 128), 256>>>(
        NQ, DFF, DMODEL, x_p, W_fc1, b_fc1, h_p);
    // 9. fc2
    sgemm_bias_kernel<false><<<dim3(DMODEL / 128, NQ / 128), 256>>>(
        NQ, DMODEL, DFF, h_p, W_fc2, b_fc2, proj_p);
    // 10. out = LN(x + h)
    add_ln_kernel<<<NQ / 8, 256>>>(x_p, proj_p, ln2g, ln2b, out);
}

// round 3
// speedup vs baseline: 1.9957x; 1.9957x over previous
#include <cuda_runtime.h>
#include <cuda_bf16.h>
#include <cstdint>

typedef __nv_bfloat16 bf16;

// ---------------------------------------------------------------------------
// Problem constants
// ---------------------------------------------------------------------------
#define NBATCH 4
#define LQ     8192
#define NQ     (NBATCH * LQ)        // 32768
#define DMODEL 256
#define NHEAD  8
#define HDIM   32
#define NLVL   4
#define NPNT   4
#define LIN    21760
#define NV     (NBATCH * LIN)       // 87040
#define DFF    1024

// ---------------------------------------------------------------------------
// Device scratch (static — no cudaMalloc allowed)
// ---------------------------------------------------------------------------
__device__ float g_value[(size_t)NV * DMODEL];
__device__ float g_off  [(size_t)NQ * DMODEL];
__device__ float g_aw   [(size_t)NQ * 128];
__device__ float g_proj [(size_t)NQ * DMODEL];
__device__ float g_x    [(size_t)NQ * DMODEL];

// bf16 hi/lo split activations
__device__ bf16 g_src_h [(size_t)NV * DMODEL];
__device__ bf16 g_src_l [(size_t)NV * DMODEL];
__device__ bf16 g_q_h   [(size_t)NQ * DMODEL];
__device__ bf16 g_q_l   [(size_t)NQ * DMODEL];
__device__ bf16 g_attn_h[(size_t)NQ * DMODEL];
__device__ bf16 g_attn_l[(size_t)NQ * DMODEL];
__device__ bf16 g_x_h   [(size_t)NQ * DMODEL];
__device__ bf16 g_x_l   [(size_t)NQ * DMODEL];
__device__ bf16 g_h_h   [(size_t)NQ * DFF];
__device__ bf16 g_h_l   [(size_t)NQ * DFF];

// transposed bf16 hi/lo weights: Wt[n][k] = W[k][n]
__device__ bf16 g_Wval_h [256 * 256],  g_Wval_l [256 * 256];
__device__ bf16 g_Woff_h [256 * 256],  g_Woff_l [256 * 256];
__device__ bf16 g_Wattn_h[128 * 256],  g_Wattn_l[128 * 256];
__device__ bf16 g_Wout_h [256 * 256],  g_Wout_l [256 * 256];
__device__ bf16 g_Wfc1_h [1024 * 256], g_Wfc1_l [1024 * 256];
__device__ bf16 g_Wfc2_h [256 * 1024], g_Wfc2_l [256 * 1024];

// ---------------------------------------------------------------------------
// PTX helpers (compute_100-safe: cp.async + ldmatrix + mma.sync only)
// ---------------------------------------------------------------------------
__device__ __forceinline__ uint32_t smem_u32(const void* p) {
    uint32_t a;
    asm("{ .reg .u64 t; cvta.to.shared.u64 t, %1; cvt.u32.u64 %0, t; }"
        : "=r"(a) : "l"(p));
    return a;
}
__device__ __forceinline__ void cp16(uint32_t saddr, const void* g) {
    asm volatile("cp.async.cg.shared.global [%0], [%1], 16;" :: "r"(saddr), "l"(g));
}
#define CP_COMMIT() asm volatile("cp.async.commit_group;" ::: "memory")
#define CP_WAIT(n)  asm volatile("cp.async.wait_group %0;" :: "n"(n) : "memory")

#define LDSM_X4(r0, r1, r2, r3, addr) \
    asm volatile("ldmatrix.sync.aligned.m8n8.x4.shared.b16 {%0,%1,%2,%3}, [%4];" \
                 : "=r"(r0), "=r"(r1), "=r"(r2), "=r"(r3) : "r"(addr))

#define MMA_BF16(d, a, b0, b1) \
    asm volatile("mma.sync.aligned.m16n8k16.row.col.f32.bf16.bf16.f32 " \
                 "{%0,%1,%2,%3}, {%4,%5,%6,%7}, {%8,%9}, {%0,%1,%2,%3};" \
                 : "+f"((d)[0]), "+f"((d)[1]), "+f"((d)[2]), "+f"((d)[3]) \
                 : "r"((a)[0]), "r"((a)[1]), "r"((a)[2]), "r"((a)[3]), \
                   "r"(b0), "r"(b1))

__device__ __forceinline__ uint32_t sw128(uint32_t off) {
    return off ^ ((off >> 3) & 0x70);
}

// ---------------------------------------------------------------------------
// bf16 split helpers
// ---------------------------------------------------------------------------
__device__ __forceinline__ void split1(float v, bf16& h, bf16& l) {
    h = __float2bfloat16(v);
    l = __float2bfloat16(v - __bfloat162float(h));
}
__device__ __forceinline__ uint32_t packbf2(bf16 a, bf16 b) {
    union { __nv_bfloat162 v; uint32_t u; } c;
    c.v = __halves2bfloat162(a, b);
    return c.u;
}

// ---------------------------------------------------------------------------
// HMMA GEMM: C[M,N] = (Ah+Al)[M,K] @ (Bh+Bl)[N,K]^T + bias   (3-term split)
// CTA tile 128x128, BK=64, 512 threads, warp tile 64x16, cp.async 2-stage.
// MODE 0: f32 out.  MODE 1: relu + bf16 hi/lo split out.
// ---------------------------------------------------------------------------
#define STAGE_BYTES 65536           // 4 tiles x 16KB
#define GSMEM_TOTAL (2 * STAGE_BYTES)

template <int MODE>
__global__ __launch_bounds__(512)
void hmma_gemm(int M, int N, int K,
               const bf16* __restrict__ Ah, const bf16* __restrict__ Al,
               const bf16* __restrict__ Bh, const bf16* __restrict__ Bl,
               const float* __restrict__ bias,
               float* __restrict__ C, bf16* __restrict__ Chi, bf16* __restrict__ Clo) {
    extern __shared__ char dsm[];
    const uint32_t sbase0 = smem_u32(dsm);
    const int tid  = threadIdx.x;
    const int wid  = tid >> 5;
    const int lane = tid & 31;
    const int wm = wid & 1;          // 0..1  -> 64-row half
    const int wn = wid >> 1;         // 0..7  -> 16-col slice
    const int row0 = blockIdx.y * 128;
    const int col0 = blockIdx.x * 128;

    // per-lane ldmatrix address components
    const int arow = wm * 64 + (lane & 15);
    const int acb  = (lane >> 4) * 16;                       // 0/16 bytes
    const int brow = wn * 16 + ((lane >> 4) & 1) * 8 + (lane & 7);
    const int bcb  = ((lane >> 3) & 1) * 16;

    float acc[4][2][4];
#pragma unroll
    for (int i = 0; i < 4; i++)
#pragma unroll
        for (int j = 0; j < 2; j++)
#pragma unroll
            for (int v = 0; v < 4; v++) acc[i][j][v] = 0.f;

    // ---- async tile loader: 4 tiles x 1024 16B segs / 512 threads = 8 each
    auto load_stage = [&](int ch, int stg) {
        const int k0 = ch << 6;
        const uint32_t sb = sbase0 + stg * STAGE_BYTES;
#pragma unroll
        for (int i = 0; i < 8; i++) {
            const int seg  = tid + i * 512;
            const int tile = seg >> 10;
            const int w    = seg & 1023;
            const int row  = w >> 3;
            const int chk  = w & 7;
            const uint32_t sw = sw128(row * 128 + chk * 16);
            const bf16* gp;
            if (tile == 0)      gp = Ah + (size_t)(row0 + row) * K + k0 + chk * 8;
            else if (tile == 1) gp = Al + (size_t)(row0 + row) * K + k0 + chk * 8;
            else if (tile == 2) gp = Bh + (size_t)(col0 + row) * K + k0 + chk * 8;
            else                gp = Bl + (size_t)(col0 + row) * K + k0 + chk * 8;
            cp16(sb + tile * 16384 + sw, gp);
        }
    };

    const int nchunk = K >> 6;
    load_stage(0, 0);
    CP_COMMIT();

    for (int ch = 0; ch < nchunk; ch++) {
        if (ch + 1 < nchunk) {
            load_stage(ch + 1, (ch + 1) & 1);
            CP_COMMIT();
            CP_WAIT(1);
        } else {
            CP_WAIT(0);
        }
        __syncthreads();

        const uint32_t sb  = sbase0 + (ch & 1) * STAGE_BYTES;
        const uint32_t sAh = sb, sAl = sb + 16384, sBh = sb + 32768, sBl = sb + 49152;

#pragma unroll
        for (int k16 = 0; k16 < 4; k16++) {
            uint32_t bh4[4], bl4[4];
            const uint32_t bo = sw128(brow * 128 + k16 * 32 + bcb);
            LDSM_X4(bh4[0], bh4[1], bh4[2], bh4[3], sBh + bo);
            LDSM_X4(bl4[0], bl4[1], bl4[2], bl4[3], sBl + bo);
            uint32_t ah[4][4], al[4][4];
#pragma unroll
            for (int mf = 0; mf < 4; mf++) {
                const uint32_t ao = sw128((arow + mf * 16) * 128 + k16 * 32 + acb);
                LDSM_X4(ah[mf][0], ah[mf][1], ah[mf][2], ah[mf][3], sAh + ao);
                LDSM_X4(al[mf][0], al[mf][1], al[mf][2], al[mf][3], sAl + ao);
            }
#pragma unroll
            for (int mf = 0; mf < 4; mf++) {
#pragma unroll
                for (int nf = 0; nf < 2; nf++) {
                    MMA_BF16(acc[mf][nf], ah[mf], bh4[nf * 2], bh4[nf * 2 + 1]);
                    MMA_BF16(acc[mf][nf], ah[mf], bl4[nf * 2], bl4[nf * 2 + 1]);
                    MMA_BF16(acc[mf][nf], al[mf], bh4[nf * 2], bh4[nf * 2 + 1]);
                }
            }
        }
        __syncthreads();
    }

    // ---- epilogue
#pragma unroll
    for (int mf = 0; mf < 4; mf++) {
        const int r = row0 + wm * 64 + mf * 16 + (lane >> 2);
#pragma unroll
        for (int nf = 0; nf < 2; nf++) {
            const int c = col0 + wn * 16 + nf * 8 + (lane & 3) * 2;
            const float b0 = __ldg(&bias[c]), b1 = __ldg(&bias[c + 1]);
#pragma unroll
            for (int hh = 0; hh < 2; hh++) {
                const int rr = r + hh * 8;
                float v0 = acc[mf][nf][hh * 2 + 0] + b0;
                float v1 = acc[mf][nf][hh * 2 + 1] + b1;
                if (MODE == 1) {
                    v0 = fmaxf(v0, 0.f);
                    v1 = fmaxf(v1, 0.f);
                    bf16 h0, l0, h1, l1;
                    split1(v0, h0, l0);
                    split1(v1, h1, l1);
                    *reinterpret_cast<uint32_t*>(Chi + (size_t)rr * N + c) = packbf2(h0, h1);
                    *reinterpret_cast<uint32_t*>(Clo + (size_t)rr * N + c) = packbf2(l0, l1);
                } else {
                    *reinterpret_cast<float2*>(C + (size_t)rr * N + c) = make_float2(v0, v1);
                }
            }
        }
    }
}

// ---------------------------------------------------------------------------
// Elementwise / conversion kernels
// ---------------------------------------------------------------------------
__global__ void add2_split_kernel(const float* __restrict__ a, const float* __restrict__ b,
                                  bf16* __restrict__ hi, bf16* __restrict__ lo, int n4) {
    int i = blockIdx.x * blockDim.x + threadIdx.x;
    if (i >= n4) return;
    float4 va = reinterpret_cast<const float4*>(a)[i];
    float4 vb = reinterpret_cast<const float4*>(b)[i];
    float v0 = va.x + vb.x, v1 = va.y + vb.y, v2 = va.z + vb.z, v3 = va.w + vb.w;
    bf16 h0, l0, h1, l1, h2, l2, h3, l3;
    split1(v0, h0, l0); split1(v1, h1, l1); split1(v2, h2, l2); split1(v3, h3, l3);
    reinterpret_cast<uint2*>(hi)[i] = make_uint2(packbf2(h0, h1), packbf2(h2, h3));
    reinterpret_cast<uint2*>(lo)[i] = make_uint2(packbf2(l0, l1), packbf2(l2, l3));
}

__global__ void split_kernel(const float* __restrict__ in,
                             bf16* __restrict__ hi, bf16* __restrict__ lo, int n4) {
    int i = blockIdx.x * blockDim.x + threadIdx.x;
    if (i >= n4) return;
    float4 v = reinterpret_cast<const float4*>(in)[i];
    bf16 h0, l0, h1, l1, h2, l2, h3, l3;
    split1(v.x, h0, l0); split1(v.y, h1, l1); split1(v.z, h2, l2); split1(v.w, h3, l3);
    reinterpret_cast<uint2*>(hi)[i] = make_uint2(packbf2(h0, h1), packbf2(h2, h3));
    reinterpret_cast<uint2*>(lo)[i] = make_uint2(packbf2(l0, l1), packbf2(l2, l3));
}

// weight transpose + split: W[K,N] -> Wt_hi/lo[N,K]
__global__ void splitT_kernel(const float* __restrict__ W,
                              bf16* __restrict__ hiT, bf16* __restrict__ loT,
                              int K, int N) {
    int o = blockIdx.x * blockDim.x + threadIdx.x;
    if (o >= K * N) return;
    int n = o / K, k = o % K;
    float v = W[(size_t)k * N + n];
    bf16 h, l;
    split1(v, h, l);
    hiT[o] = h; loT[o] = l;
}

__global__ void mask_zero_kernel(const unsigned char* __restrict__ mask,
                                 float* __restrict__ value) {
    int row  = blockIdx.x * 8 + (threadIdx.x >> 5);
    int lane = threadIdx.x & 31;
    if (row >= NV) return;
    if (mask[row]) {
        float* v = value + (size_t)row * DMODEL;
        for (int c = lane; c < DMODEL; c += 32) v[c] = 0.f;
    }
}

__global__ void softmax16_kernel(float* __restrict__ aw) {
    int idx = blockIdx.x * blockDim.x + threadIdx.x;
    if (idx >= NQ * NHEAD) return;
    float* a = aw + (size_t)idx * 16;
    float v[16];
    float m = -1e30f;
#pragma unroll
    for (int i = 0; i < 16; i++) { v[i] = a[i]; m = fmaxf(m, v[i]); }
    float s = 0.f;
#pragma unroll
    for (int i = 0; i < 16; i++) { v[i] = expf(v[i] - m); s += v[i]; }
    float inv = 1.f / s;
#pragma unroll
    for (int i = 0; i < 16; i++) a[i] = v[i] * inv;
}

// ---------------------------------------------------------------------------
// Deformable sampling; writes attn bf16 hi/lo split directly.
// One warp per (n, q, head); lane = channel.
// ---------------------------------------------------------------------------
__global__ __launch_bounds__(256)
void deform_sample_kernel(const float* __restrict__ value,
                          const float* __restrict__ off,
                          const float* __restrict__ aw,
                          const float* __restrict__ refp,
                          bf16* __restrict__ out_h, bf16* __restrict__ out_l) {
    const int gw   = (blockIdx.x * blockDim.x + threadIdx.x) >> 5;
    const int lane = threadIdx.x & 31;
    if (gw >= NQ * NHEAD) return;
    const int h  = gw & (NHEAD - 1);
    const int nq = gw >> 3;
    const int n  = nq / LQ;

    const int HW[4]  = {128, 64, 32, 16};
    const int LST[4] = {0, 16384, 20480, 21504};

    const float* offr  = off  + (size_t)nq * 256 + h * 32;
    const float* awr   = aw   + (size_t)nq * 128 + h * 16;
    const float* refr  = refp + (size_t)nq * 8;
    const float* vbase = value + (size_t)n * LIN * DMODEL + h * HDIM + lane;

    float acc = 0.f;
#pragma unroll
    for (int l = 0; l < NLVL; l++) {
        const int   Hl = HW[l];
        const float rx = refr[l * 2 + 0] * (float)Hl - 0.5f;
        const float ry = refr[l * 2 + 1] * (float)Hl - 0.5f;
        const float* vl = vbase + (size_t)LST[l] * DMODEL;
#pragma unroll
        for (int p = 0; p < NPNT; p++) {
            const float px = rx + offr[(l * NPNT + p) * 2 + 0];
            const float py = ry + offr[(l * NPNT + p) * 2 + 1];
            const float w  = awr[l * NPNT + p];
            const float x0f = floorf(px), y0f = floorf(py);
            const float dx = px - x0f, dy = py - y0f;
            const int x0 = (int)x0f, y0 = (int)y0f;
            const float cw[4] = {(1.f - dx) * (1.f - dy), dx * (1.f - dy),
                                 (1.f - dx) * dy,         dx * dy};
            const int cx[4] = {x0, x0 + 1, x0, x0 + 1};
            const int cy[4] = {y0, y0, y0 + 1, y0 + 1};
#pragma unroll
            for (int c = 0; c < 4; c++) {
                if (cx[c] >= 0 && cx[c] < Hl && cy[c] >= 0 && cy[c] < Hl) {
                    acc = fmaf(w * cw[c], vl[(size_t)(cy[c] * Hl + cx[c]) * DMODEL], acc);
                }
            }
        }
    }
    bf16 hh, ll;
    split1(acc, hh, ll);
    const size_t oidx = (size_t)nq * DMODEL + h * HDIM + lane;
    out_h[oidx] = hh;
    out_l[oidx] = ll;
}

// ---------------------------------------------------------------------------
// Fused residual add + LayerNorm (D=256), optional bf16 split output
// ---------------------------------------------------------------------------
template <bool SPLIT>
__global__ __launch_bounds__(256)
void add_ln_kernel(const float* __restrict__ a, const float* __restrict__ b,
                   const float* __restrict__ g, const float* __restrict__ beta,
                   float* __restrict__ out, bf16* __restrict__ out_h,
                   bf16* __restrict__ out_l) {
    const int row  = blockIdx.x * 8 + (threadIdx.x >> 5);
    const int lane = threadIdx.x & 31;
    if (row >= NQ) return;
    const float4* ar = reinterpret_cast<const float4*>(a + (size_t)row * DMODEL);
    const float4* br = reinterpret_cast<const float4*>(b + (size_t)row * DMODEL);

    float xv[8];
    float s = 0.f, s2 = 0.f;
#pragma unroll
    for (int t = 0; t < 2; t++) {
        float4 u = ar[lane + t * 32];
        float4 w = br[lane + t * 32];
        xv[t * 4 + 0] = u.x + w.x;
        xv[t * 4 + 1] = u.y + w.y;
        xv[t * 4 + 2] = u.z + w.z;
        xv[t * 4 + 3] = u.w + w.w;
#pragma unroll
        for (int j = 0; j < 4; j++) {
            float v = xv[t * 4 + j];
            s += v; s2 = fmaf(v, v, s2);
        }
    }
#pragma unroll
    for (int o = 16; o > 0; o >>= 1) {
        s  += __shfl_xor_sync(0xFFFFFFFFu, s, o);
        s2 += __shfl_xor_sync(0xFFFFFFFFu, s2, o);
    }
    const float mean = s * (1.f / DMODEL);
    const float var  = s2 * (1.f / DMODEL) - mean * mean;
    const float inv  = rsqrtf(var + 1e-5f);

    const float4* gr = reinterpret_cast<const float4*>(g);
    const float4* be = reinterpret_cast<const float4*>(beta);
#pragma unroll
    for (int t = 0; t < 2; t++) {
        float4 gv = gr[lane + t * 32];
        float4 bv = be[lane + t * 32];
        float o0 = (xv[t * 4 + 0] - mean) * inv * gv.x + bv.x;
        float o1 = (xv[t * 4 + 1] - mean) * inv * gv.y + bv.y;
        float o2 = (xv[t * 4 + 2] - mean) * inv * gv.z + bv.z;
        float o3 = (xv[t * 4 + 3] - mean) * inv * gv.w + bv.w;
        reinterpret_cast<float4*>(out + (size_t)row * DMODEL)[lane + t * 32] =
            make_float4(o0, o1, o2, o3);
        if (SPLIT) {
            bf16 h0, l0, h1, l1, h2, l2, h3, l3;
            split1(o0, h0, l0); split1(o1, h1, l1);
            split1(o2, h2, l2); split1(o3, h3, l3);
            reinterpret_cast<uint2*>(out_h + (size_t)row * DMODEL)[lane + t * 32] =
                make_uint2(packbf2(h0, h1), packbf2(h2, h3));
            reinterpret_cast<uint2*>(out_l + (size_t)row * DMODEL)[lane + t * 32] =
                make_uint2(packbf2(l0, l1), packbf2(l2, l3));
        }
    }
}

// ---------------------------------------------------------------------------
// kernel_launch
// ---------------------------------------------------------------------------
extern "C" void kernel_launch(void* const* d_in, const int* in_sizes, int n_in,
                              void* d_out, int out_size) {
    const float*         tgt    = (const float*)d_in[0];
    const float*         qpos   = (const float*)d_in[1];
    const float*         refp   = (const float*)d_in[2];
    const float*         src    = (const float*)d_in[3];
    const unsigned char* mask   = (const unsigned char*)d_in[6];
    const float*         W_off  = (const float*)d_in[7];
    const float*         b_off  = (const float*)d_in[8];
    const float*         W_attn = (const float*)d_in[9];
    const float*         b_attn = (const float*)d_in[10];
    const float*         W_val  = (const float*)d_in[11];
    const float*         b_val  = (const float*)d_in[12];
    const float*         W_out  = (const float*)d_in[13];
    const float*         b_out  = (const float*)d_in[14];
    const float*         ln1g   = (const float*)d_in[15];
    const float*         ln1b   = (const float*)d_in[16];
    const float*         W_fc1  = (const float*)d_in[17];
    const float*         b_fc1  = (const float*)d_in[18];
    const float*         W_fc2  = (const float*)d_in[19];
    const float*         b_fc2  = (const float*)d_in[20];
    const float*         ln2g   = (const float*)d_in[21];
    const float*         ln2b   = (const float*)d_in[22];
    float*               out    = (float*)d_out;

    float *value_p, *off_p, *aw_p, *proj_p, *x_p;
    bf16 *srch, *srcl, *qh, *ql, *ath, *atl, *xh, *xl, *hh, *hl;
    bf16 *wvh, *wvl, *woh, *wol, *wah, *wal, *wuh, *wul, *w1h, *w1l, *w2h, *w2l;
    cudaGetSymbolAddress((void**)&value_p, g_value);
    cudaGetSymbolAddress((void**)&off_p,   g_off);
    cudaGetSymbolAddress((void**)&aw_p,    g_aw);
    cudaGetSymbolAddress((void**)&proj_p,  g_proj);
    cudaGetSymbolAddress((void**)&x_p,     g_x);
    cudaGetSymbolAddress((void**)&srch, g_src_h);  cudaGetSymbolAddress((void**)&srcl, g_src_l);
    cudaGetSymbolAddress((void**)&qh,   g_q_h);    cudaGetSymbolAddress((void**)&ql,   g_q_l);
    cudaGetSymbolAddress((void**)&ath,  g_attn_h); cudaGetSymbolAddress((void**)&atl,  g_attn_l);
    cudaGetSymbolAddress((void**)&xh,   g_x_h);    cudaGetSymbolAddress((void**)&xl,   g_x_l);
    cudaGetSymbolAddress((void**)&hh,   g_h_h);    cudaGetSymbolAddress((void**)&hl,   g_h_l);
    cudaGetSymbolAddress((void**)&wvh, g_Wval_h);  cudaGetSymbolAddress((void**)&wvl, g_Wval_l);
    cudaGetSymbolAddress((void**)&woh, g_Woff_h);  cudaGetSymbolAddress((void**)&wol, g_Woff_l);
    cudaGetSymbolAddress((void**)&wah, g_Wattn_h); cudaGetSymbolAddress((void**)&wal, g_Wattn_l);
    cudaGetSymbolAddress((void**)&wuh, g_Wout_h);  cudaGetSymbolAddress((void**)&wul, g_Wout_l);
    cudaGetSymbolAddress((void**)&w1h, g_Wfc1_h);  cudaGetSymbolAddress((void**)&w1l, g_Wfc1_l);
    cudaGetSymbolAddress((void**)&w2h, g_Wfc2_h);  cudaGetSymbolAddress((void**)&w2l, g_Wfc2_l);

    cudaFuncSetAttribute(hmma_gemm<0>, cudaFuncAttributeMaxDynamicSharedMemorySize, GSMEM_TOTAL);
    cudaFuncSetAttribute(hmma_gemm<1>, cudaFuncAttributeMaxDynamicSharedMemorySize, GSMEM_TOTAL);

    // weight conversions (transpose + split)
    splitT_kernel<<<(256 * 256 + 255) / 256, 256>>>(W_val,  wvh, wvl, 256, 256);
    splitT_kernel<<<(256 * 256 + 255) / 256, 256>>>(W_off,  woh, wol, 256, 256);
    splitT_kernel<<<(256 * 128 + 255) / 256, 256>>>(W_attn, wah, wal, 256, 128);
    splitT_kernel<<<(256 * 256 + 255) / 256, 256>>>(W_out,  wuh, wul, 256, 256);
    splitT_kernel<<<(256 * 1024 + 255) / 256, 256>>>(W_fc1, w1h, w1l, 256, 1024);
    splitT_kernel<<<(1024 * 256 + 255) / 256, 256>>>(W_fc2, w2h, w2l, 1024, 256);
    // src split + q = tgt + pos (split)
    split_kernel<<<(NV * DMODEL / 4 + 255) / 256, 256>>>(src, srch, srcl, NV * DMODEL / 4);
    add2_split_kernel<<<(NQ * DMODEL / 4 + 255) / 256, 256>>>(tgt, qpos, qh, ql,
                                                              NQ * DMODEL / 4);
    // value = src @ W_val + b_val
    hmma_gemm<0><<<dim3(2, NV / 128), 512, GSMEM_TOTAL>>>(
        NV, 256, 256, srch, srcl, wvh, wvl, b_val, value_p, nullptr, nullptr);
    mask_zero_kernel<<<(NV + 7) / 8, 256>>>(mask, value_p);
    // off = q @ W_off + b_off
    hmma_gemm<0><<<dim3(2, NQ / 128), 512, GSMEM_TOTAL>>>(
        NQ, 256, 256, qh, ql, woh, wol, b_off, off_p, nullptr, nullptr);
    // aw = q @ W_attn + b_attn; softmax
    hmma_gemm<0><<<dim3(1, NQ / 128), 512, GSMEM_TOTAL>>>(
        NQ, 128, 256, qh, ql, wah, wal, b_attn, aw_p, nullptr, nullptr);
    softmax16_kernel<<<(NQ * NHEAD + 255) / 256, 256>>>(aw_p);
    // sampling -> attn (bf16 split)
    deform_sample_kernel<<<NQ * NHEAD / 8, 256>>>(value_p, off_p, aw_p, refp, ath, atl);
    // proj = attn @ W_out + b_out
    hmma_gemm<0><<<dim3(2, NQ / 128), 512, GSMEM_TOTAL>>>(
        NQ, 256, 256, ath, atl, wuh, wul, b_out, proj_p, nullptr, nullptr);
    // x = LN(tgt + proj) (+ split)
    add_ln_kernel<true><<<NQ / 8, 256>>>(tgt, proj_p, ln1g, ln1b, x_p, xh, xl);
    // h = relu(x @ W_fc1 + b_fc1) -> bf16 split only
    hmma_gemm<1><<<dim3(DFF / 128, NQ / 128), 512, GSMEM_TOTAL>>>(
        NQ, DFF, 256, xh, xl, w1h, w1l, b_fc1, nullptr, hh, hl);
    // proj = h @ W_fc2 + b_fc2
    hmma_gemm<0><<<dim3(2, NQ / 128), 512, GSMEM_TOTAL>>>(
        NQ, 256, DFF, hh, hl, w2h, w2l, b_fc2, proj_p, nullptr, nullptr);
    // out = LN(x + proj)
    add_ln_kernel<false><<<NQ / 8, 256>>>(x_p, proj_p, ln2g, ln2b, out, nullptr, nullptr);
}

// round 4
// speedup vs baseline: 2.8127x; 1.4094x over previous
#include <cuda_runtime.h>
#include <cuda_fp16.h>
#include <cstdint>

typedef __half fp16;

// ---------------------------------------------------------------------------
// Problem constants
// ---------------------------------------------------------------------------
#define NBATCH 4
#define LQ     8192
#define NQ     (NBATCH * LQ)        // 32768
#define DMODEL 256
#define NHEAD  8
#define HDIM   32
#define NLVL   4
#define NPNT   4
#define LIN    21760
#define NV     (NBATCH * LIN)       // 87040
#define DFF    1024
#define NOA    384                  // 256 off + 128 attn fused

// ---------------------------------------------------------------------------
// Device scratch (static — no cudaMalloc allowed)
// ---------------------------------------------------------------------------
__device__ float g_value[(size_t)NV * DMODEL];
__device__ float g_offaw[(size_t)NQ * NOA];
__device__ float g_proj [(size_t)NQ * DMODEL];
__device__ float g_x    [(size_t)NQ * DMODEL];

// fp16 activations
__device__ fp16 g_src16 [(size_t)NV * DMODEL];
__device__ fp16 g_q16   [(size_t)NQ * DMODEL];
__device__ fp16 g_attn16[(size_t)NQ * DMODEL];
__device__ fp16 g_x16   [(size_t)NQ * DMODEL];
__device__ fp16 g_h16   [(size_t)NQ * DFF];

// transposed fp16 weights: Wt[n][k] = W[k][n]
__device__ fp16  g_Wval [256 * 256];
__device__ fp16  g_Woa  [NOA * 256];
__device__ fp16  g_Wout [256 * 256];
__device__ fp16  g_Wfc1 [1024 * 256];
__device__ fp16  g_Wfc2 [256 * 1024];
__device__ float g_boa  [NOA];

// ---------------------------------------------------------------------------
// PTX helpers (compute_100-safe: cp.async + ldmatrix + mma.sync)
// ---------------------------------------------------------------------------
__device__ __forceinline__ uint32_t smem_u32(const void* p) {
    uint32_t a;
    asm("{ .reg .u64 t; cvta.to.shared.u64 t, %1; cvt.u32.u64 %0, t; }"
        : "=r"(a) : "l"(p));
    return a;
}
__device__ __forceinline__ void cp16(uint32_t saddr, const void* g) {
    asm volatile("cp.async.cg.shared.global [%0], [%1], 16;" :: "r"(saddr), "l"(g));
}
#define CP_COMMIT() asm volatile("cp.async.commit_group;" ::: "memory")
#define CP_WAIT(n)  asm volatile("cp.async.wait_group %0;" :: "n"(n) : "memory")

#define LDSM_X4(r0, r1, r2, r3, addr) \
    asm volatile("ldmatrix.sync.aligned.m8n8.x4.shared.b16 {%0,%1,%2,%3}, [%4];" \
                 : "=r"(r0), "=r"(r1), "=r"(r2), "=r"(r3) : "r"(addr))

#define MMA_FP16(d, a, b0, b1) \
    asm volatile("mma.sync.aligned.m16n8k16.row.col.f32.f16.f16.f32 " \
                 "{%0,%1,%2,%3}, {%4,%5,%6,%7}, {%8,%9}, {%0,%1,%2,%3};" \
                 : "+f"((d)[0]), "+f"((d)[1]), "+f"((d)[2]), "+f"((d)[3]) \
                 : "r"((a)[0]), "r"((a)[1]), "r"((a)[2]), "r"((a)[3]), \
                   "r"(b0), "r"(b1))

__device__ __forceinline__ uint32_t sw128(uint32_t off) {
    return off ^ ((off >> 3) & 0x70);
}
__device__ __forceinline__ uint32_t packh2(fp16 a, fp16 b) {
    union { __half2 v; uint32_t u; } c;
    c.v = __halves2half2(a, b);
    return c.u;
}

// ---------------------------------------------------------------------------
// HMMA GEMM (single fp16): C[M,N] = A[M,K] @ B[N,K]^T + bias
// CTA tile 128x128, BK=64, 512 threads, warp tile 64x16, cp.async 2-stage.
// MODE 0: f32 out.  MODE 1: relu + fp16 out.
// ---------------------------------------------------------------------------
#define STAGE_BYTES 32768           // 2 tiles x 16KB
#define GSMEM_TOTAL (2 * STAGE_BYTES)

template <int MODE>
__global__ __launch_bounds__(512)
void hmma_gemm(int M, int N, int K,
               const fp16* __restrict__ A, const fp16* __restrict__ B,
               const float* __restrict__ bias,
               float* __restrict__ C, fp16* __restrict__ Ch) {
    extern __shared__ char dsm[];
    const uint32_t sbase0 = smem_u32(dsm);
    const int tid  = threadIdx.x;
    const int wid  = tid >> 5;
    const int lane = tid & 31;
    const int wm = wid & 1;          // 0..1  -> 64-row half
    const int wn = wid >> 1;         // 0..7  -> 16-col slice
    const int row0 = blockIdx.y * 128;
    const int col0 = blockIdx.x * 128;

    const int arow = wm * 64 + (lane & 15);
    const int acb  = (lane >> 4) * 16;
    const int brow = wn * 16 + ((lane >> 4) & 1) * 8 + (lane & 7);
    const int bcb  = ((lane >> 3) & 1) * 16;

    float acc[4][2][4];
#pragma unroll
    for (int i = 0; i < 4; i++)
#pragma unroll
        for (int j = 0; j < 2; j++)
#pragma unroll
            for (int v = 0; v < 4; v++) acc[i][j][v] = 0.f;

    // 2 tiles x 1024 segs of 16B / 512 threads = 4 per thread
    auto load_stage = [&](int ch, int stg) {
        const int k0 = ch << 6;
        const uint32_t sb = sbase0 + stg * STAGE_BYTES;
#pragma unroll
        for (int i = 0; i < 4; i++) {
            const int seg  = tid + i * 512;
            const int tile = seg >> 10;
            const int w    = seg & 1023;
            const int row  = w >> 3;
            const int chk  = w & 7;
            const uint32_t sw = sw128(row * 128 + chk * 16);
            const fp16* gp = tile == 0 ? A + (size_t)(row0 + row) * K + k0 + chk * 8
                                       : B + (size_t)(col0 + row) * K + k0 + chk * 8;
            cp16(sb + tile * 16384 + sw, gp);
        }
    };

    const int nchunk = K >> 6;
    load_stage(0, 0);
    CP_COMMIT();

    for (int ch = 0; ch < nchunk; ch++) {
        if (ch + 1 < nchunk) {
            load_stage(ch + 1, (ch + 1) & 1);
            CP_COMMIT();
            CP_WAIT(1);
        } else {
            CP_WAIT(0);
        }
        __syncthreads();

        const uint32_t sb = sbase0 + (ch & 1) * STAGE_BYTES;
        const uint32_t sA = sb, sB = sb + 16384;

#pragma unroll
        for (int k16 = 0; k16 < 4; k16++) {
            uint32_t b4[4];
            const uint32_t bo = sw128(brow * 128 + k16 * 32 + bcb);
            LDSM_X4(b4[0], b4[1], b4[2], b4[3], sB + bo);
            uint32_t af[4][4];
#pragma unroll
            for (int mf = 0; mf < 4; mf++) {
                const uint32_t ao = sw128((arow + mf * 16) * 128 + k16 * 32 + acb);
                LDSM_X4(af[mf][0], af[mf][1], af[mf][2], af[mf][3], sA + ao);
            }
#pragma unroll
            for (int mf = 0; mf < 4; mf++) {
#pragma unroll
                for (int nf = 0; nf < 2; nf++) {
                    MMA_FP16(acc[mf][nf], af[mf], b4[nf * 2], b4[nf * 2 + 1]);
                }
            }
        }
        __syncthreads();
    }

    // epilogue
#pragma unroll
    for (int mf = 0; mf < 4; mf++) {
        const int r = row0 + wm * 64 + mf * 16 + (lane >> 2);
#pragma unroll
        for (int nf = 0; nf < 2; nf++) {
            const int c = col0 + wn * 16 + nf * 8 + (lane & 3) * 2;
            const float b0 = __ldg(&bias[c]), b1 = __ldg(&bias[c + 1]);
#pragma unroll
            for (int hh = 0; hh < 2; hh++) {
                const int rr = r + hh * 8;
                float v0 = acc[mf][nf][hh * 2 + 0] + b0;
                float v1 = acc[mf][nf][hh * 2 + 1] + b1;
                if (MODE == 1) {
                    v0 = fmaxf(v0, 0.f);
                    v1 = fmaxf(v1, 0.f);
                    *reinterpret_cast<uint32_t*>(Ch + (size_t)rr * N + c) =
                        packh2(__float2half(v0), __float2half(v1));
                } else {
                    *reinterpret_cast<float2*>(C + (size_t)rr * N + c) = make_float2(v0, v1);
                }
            }
        }
    }
}

// ---------------------------------------------------------------------------
// Elementwise / conversion kernels
// ---------------------------------------------------------------------------
__global__ void add2_h_kernel(const float* __restrict__ a, const float* __restrict__ b,
                              fp16* __restrict__ o, int n4) {
    int i = blockIdx.x * blockDim.x + threadIdx.x;
    if (i >= n4) return;
    float4 va = reinterpret_cast<const float4*>(a)[i];
    float4 vb = reinterpret_cast<const float4*>(b)[i];
    reinterpret_cast<uint2*>(o)[i] = make_uint2(
        packh2(__float2half(va.x + vb.x), __float2half(va.y + vb.y)),
        packh2(__float2half(va.z + vb.z), __float2half(va.w + vb.w)));
}

__global__ void tohalf_kernel(const float* __restrict__ in, fp16* __restrict__ o, int n4) {
    int i = blockIdx.x * blockDim.x + threadIdx.x;
    if (i >= n4) return;
    float4 v = reinterpret_cast<const float4*>(in)[i];
    reinterpret_cast<uint2*>(o)[i] = make_uint2(
        packh2(__float2half(v.x), __float2half(v.y)),
        packh2(__float2half(v.z), __float2half(v.w)));
}

// weight transpose: W[K,N] -> Wt[N,K] fp16
__global__ void splitT_kernel(const float* __restrict__ W, fp16* __restrict__ Wt,
                              int K, int N) {
    int o = blockIdx.x * blockDim.x + threadIdx.x;
    if (o >= K * N) return;
    int n = o / K, k = o % K;
    Wt[o] = __float2half(W[(size_t)k * N + n]);
}

// fused off+attn weight: Woa[384][256]
__global__ void splitT_oa_kernel(const float* __restrict__ Woff,
                                 const float* __restrict__ Wattn,
                                 fp16* __restrict__ Wt) {
    int o = blockIdx.x * blockDim.x + threadIdx.x;
    if (o >= NOA * 256) return;
    int n = o / 256, k = o % 256;
    float v = (n < 256) ? Woff[(size_t)k * 256 + n] : Wattn[(size_t)k * 128 + (n - 256)];
    Wt[o] = __float2half(v);
}

__global__ void concat_bias_kernel(const float* __restrict__ b_off,
                                   const float* __restrict__ b_attn,
                                   float* __restrict__ b_oa) {
    int i = threadIdx.x + blockIdx.x * blockDim.x;
    if (i >= NOA) return;
    b_oa[i] = (i < 256) ? b_off[i] : b_attn[i - 256];
}

__global__ void mask_zero_kernel(const unsigned char* __restrict__ mask,
                                 float* __restrict__ value) {
    int row  = blockIdx.x * 8 + (threadIdx.x >> 5);
    int lane = threadIdx.x & 31;
    if (row >= NV) return;
    if (mask[row]) {
        float* v = value + (size_t)row * DMODEL;
        for (int c = lane; c < DMODEL; c += 32) v[c] = 0.f;
    }
}

// softmax over 16 logits at offaw[row*384 + 256 + h*16]
__global__ void softmax16_kernel(float* __restrict__ offaw) {
    int idx = blockIdx.x * blockDim.x + threadIdx.x;
    if (idx >= NQ * NHEAD) return;
    float* a = offaw + (size_t)(idx >> 3) * NOA + 256 + (idx & 7) * 16;
    float v[16];
    float m = -1e30f;
#pragma unroll
    for (int i = 0; i < 16; i++) { v[i] = a[i]; m = fmaxf(m, v[i]); }
    float s = 0.f;
#pragma unroll
    for (int i = 0; i < 16; i++) { v[i] = expf(v[i] - m); s += v[i]; }
    float inv = 1.f / s;
#pragma unroll
    for (int i = 0; i < 16; i++) a[i] = v[i] * inv;
}

// ---------------------------------------------------------------------------
// Deformable sampling; writes attn fp16.
// ---------------------------------------------------------------------------
__global__ __launch_bounds__(256)
void deform_sample_kernel(const float* __restrict__ value,
                          const float* __restrict__ offaw,
                          const float* __restrict__ refp,
                          fp16* __restrict__ out_h) {
    const int gw   = (blockIdx.x * blockDim.x + threadIdx.x) >> 5;
    const int lane = threadIdx.x & 31;
    if (gw >= NQ * NHEAD) return;
    const int h  = gw & (NHEAD - 1);
    const int nq = gw >> 3;
    const int n  = nq / LQ;

    const int HW[4]  = {128, 64, 32, 16};
    const int LST[4] = {0, 16384, 20480, 21504};

    const float* offr  = offaw + (size_t)nq * NOA + h * 32;
    const float* awr   = offaw + (size_t)nq * NOA + 256 + h * 16;
    const float* refr  = refp + (size_t)nq * 8;
    const float* vbase = value + (size_t)n * LIN * DMODEL + h * HDIM + lane;

    float acc = 0.f;
#pragma unroll
    for (int l = 0; l < NLVL; l++) {
        const int   Hl = HW[l];
        const float rx = refr[l * 2 + 0] * (float)Hl - 0.5f;
        const float ry = refr[l * 2 + 1] * (float)Hl - 0.5f;
        const float* vl = vbase + (size_t)LST[l] * DMODEL;
#pragma unroll
        for (int p = 0; p < NPNT; p++) {
            const float px = rx + offr[(l * NPNT + p) * 2 + 0];
            const float py = ry + offr[(l * NPNT + p) * 2 + 1];
            const float w  = awr[l * NPNT + p];
            const float x0f = floorf(px), y0f = floorf(py);
            const float dx = px - x0f, dy = py - y0f;
            const int x0 = (int)x0f, y0 = (int)y0f;
            const float cw[4] = {(1.f - dx) * (1.f - dy), dx * (1.f - dy),
                                 (1.f - dx) * dy,         dx * dy};
            const int cx[4] = {x0, x0 + 1, x0, x0 + 1};
            const int cy[4] = {y0, y0, y0 + 1, y0 + 1};
#pragma unroll
            for (int c = 0; c < 4; c++) {
                if (cx[c] >= 0 && cx[c] < Hl && cy[c] >= 0 && cy[c] < Hl) {
                    acc = fmaf(w * cw[c], vl[(size_t)(cy[c] * Hl + cx[c]) * DMODEL], acc);
                }
            }
        }
    }
    out_h[(size_t)nq * DMODEL + h * HDIM + lane] = __float2half(acc);
}

// ---------------------------------------------------------------------------
// Fused residual add + LayerNorm (D=256), optional fp16 copy
// ---------------------------------------------------------------------------
template <bool TOH>
__global__ __launch_bounds__(256)
void add_ln_kernel(const float* __restrict__ a, const float* __restrict__ b,
                   const float* __restrict__ g, const float* __restrict__ beta,
                   float* __restrict__ out, fp16* __restrict__ out_h) {
    const int row  = blockIdx.x * 8 + (threadIdx.x >> 5);
    const int lane = threadIdx.x & 31;
    if (row >= NQ) return;
    const float4* ar = reinterpret_cast<const float4*>(a + (size_t)row * DMODEL);
    const float4* br = reinterpret_cast<const float4*>(b + (size_t)row * DMODEL);

    float xv[8];
    float s = 0.f, s2 = 0.f;
#pragma unroll
    for (int t = 0; t < 2; t++) {
        float4 u = ar[lane + t * 32];
        float4 w = br[lane + t * 32];
        xv[t * 4 + 0] = u.x + w.x;
        xv[t * 4 + 1] = u.y + w.y;
        xv[t * 4 + 2] = u.z + w.z;
        xv[t * 4 + 3] = u.w + w.w;
#pragma unroll
        for (int j = 0; j < 4; j++) {
            float v = xv[t * 4 + j];
            s += v; s2 = fmaf(v, v, s2);
        }
    }
#pragma unroll
    for (int o = 16; o > 0; o >>= 1) {
        s  += __shfl_xor_sync(0xFFFFFFFFu, s, o);
        s2 += __shfl_xor_sync(0xFFFFFFFFu, s2, o);
    }
    const float mean = s * (1.f / DMODEL);
    const float var  = s2 * (1.f / DMODEL) - mean * mean;
    const float inv  = rsqrtf(var + 1e-5f);

    const float4* gr = reinterpret_cast<const float4*>(g);
    const float4* be = reinterpret_cast<const float4*>(beta);
#pragma unroll
    for (int t = 0; t < 2; t++) {
        float4 gv = gr[lane + t * 32];
        float4 bv = be[lane + t * 32];
        float o0 = (xv[t * 4 + 0] - mean) * inv * gv.x + bv.x;
        float o1 = (xv[t * 4 + 1] - mean) * inv * gv.y + bv.y;
        float o2 = (xv[t * 4 + 2] - mean) * inv * gv.z + bv.z;
        float o3 = (xv[t * 4 + 3] - mean) * inv * gv.w + bv.w;
        reinterpret_cast<float4*>(out + (size_t)row * DMODEL)[lane + t * 32] =
            make_float4(o0, o1, o2, o3);
        if (TOH) {
            reinterpret_cast<uint2*>(out_h + (size_t)row * DMODEL)[lane + t * 32] =
                make_uint2(packh2(__float2half(o0), __float2half(o1)),
                           packh2(__float2half(o2), __float2half(o3)));
        }
    }
}

// ---------------------------------------------------------------------------
// kernel_launch
// ---------------------------------------------------------------------------
extern "C" void kernel_launch(void* const* d_in, const int* in_sizes, int n_in,
                              void* d_out, int out_size) {
    const float*         tgt    = (const float*)d_in[0];
    const float*         qpos   = (const float*)d_in[1];
    const float*         refp   = (const float*)d_in[2];
    const float*         src    = (const float*)d_in[3];
    const unsigned char* mask   = (const unsigned char*)d_in[6];
    const float*         W_off  = (const float*)d_in[7];
    const float*         b_off  = (const float*)d_in[8];
    const float*         W_attn = (const float*)d_in[9];
    const float*         b_attn = (const float*)d_in[10];
    const float*         W_val  = (const float*)d_in[11];
    const float*         b_val  = (const float*)d_in[12];
    const float*         W_out  = (const float*)d_in[13];
    const float*         b_out  = (const float*)d_in[14];
    const float*         ln1g   = (const float*)d_in[15];
    const float*         ln1b   = (const float*)d_in[16];
    const float*         W_fc1  = (const float*)d_in[17];
    const float*         b_fc1  = (const float*)d_in[18];
    const float*         W_fc2  = (const float*)d_in[19];
    const float*         b_fc2  = (const float*)d_in[20];
    const float*         ln2g   = (const float*)d_in[21];
    const float*         ln2b   = (const float*)d_in[22];
    float*               out    = (float*)d_out;

    float *value_p, *offaw_p, *proj_p, *x_p, *boa_p;
    fp16 *src16, *q16, *at16, *x16, *h16;
    fp16 *wv, *woa, *wu, *w1, *w2;
    cudaGetSymbolAddress((void**)&value_p, g_value);
    cudaGetSymbolAddress((void**)&offaw_p, g_offaw);
    cudaGetSymbolAddress((void**)&proj_p,  g_proj);
    cudaGetSymbolAddress((void**)&x_p,     g_x);
    cudaGetSymbolAddress((void**)&boa_p,   g_boa);
    cudaGetSymbolAddress((void**)&src16, g_src16);
    cudaGetSymbolAddress((void**)&q16,   g_q16);
    cudaGetSymbolAddress((void**)&at16,  g_attn16);
    cudaGetSymbolAddress((void**)&x16,   g_x16);
    cudaGetSymbolAddress((void**)&h16,   g_h16);
    cudaGetSymbolAddress((void**)&wv,  g_Wval);
    cudaGetSymbolAddress((void**)&woa, g_Woa);
    cudaGetSymbolAddress((void**)&wu,  g_Wout);
    cudaGetSymbolAddress((void**)&w1,  g_Wfc1);
    cudaGetSymbolAddress((void**)&w2,  g_Wfc2);

    cudaFuncSetAttribute(hmma_gemm<0>, cudaFuncAttributeMaxDynamicSharedMemorySize, GSMEM_TOTAL);
    cudaFuncSetAttribute(hmma_gemm<1>, cudaFuncAttributeMaxDynamicSharedMemorySize, GSMEM_TOTAL);

    // weight conversions
    splitT_kernel<<<(256 * 256 + 255) / 256, 256>>>(W_val, wv, 256, 256);
    splitT_oa_kernel<<<(NOA * 256 + 255) / 256, 256>>>(W_off, W_attn, woa);
    concat_bias_kernel<<<2, 256>>>(b_off, b_attn, boa_p);
    splitT_kernel<<<(256 * 256 + 255) / 256, 256>>>(W_out, wu, 256, 256);
    splitT_kernel<<<(256 * 1024 + 255) / 256, 256>>>(W_fc1, w1, 256, 1024);
    splitT_kernel<<<(1024 * 256 + 255) / 256, 256>>>(W_fc2, w2, 1024, 256);
    // activation conversions
    tohalf_kernel<<<(NV * DMODEL / 4 + 255) / 256, 256>>>(src, src16, NV * DMODEL / 4);
    add2_h_kernel<<<(NQ * DMODEL / 4 + 255) / 256, 256>>>(tgt, qpos, q16, NQ * DMODEL / 4);
    // value = src @ W_val + b_val
    hmma_gemm<0><<<dim3(2, NV / 128), 512, GSMEM_TOTAL>>>(
        NV, 256, 256, src16, wv, b_val, value_p, nullptr);
    mask_zero_kernel<<<(NV + 7) / 8, 256>>>(mask, value_p);
    // offaw = q @ [W_off | W_attn] + [b_off | b_attn]
    hmma_gemm<0><<<dim3(3, NQ / 128), 512, GSMEM_TOTAL>>>(
        NQ, NOA, 256, q16, woa, boa_p, offaw_p, nullptr);
    softmax16_kernel<<<(NQ * NHEAD + 255) / 256, 256>>>(offaw_p);
    // sampling -> attn fp16
    deform_sample_kernel<<<NQ * NHEAD / 8, 256>>>(value_p, offaw_p, refp, at16);
    // proj = attn @ W_out + b_out
    hmma_gemm<0><<<dim3(2, NQ / 128), 512, GSMEM_TOTAL>>>(
        NQ, 256, 256, at16, wu, b_out, proj_p, nullptr);
    // x = LN(tgt + proj) (+ fp16)
    add_ln_kernel<true><<<NQ / 8, 256>>>(tgt, proj_p, ln1g, ln1b, x_p, x16);
    // h = relu(x @ W_fc1 + b_fc1) -> fp16
    hmma_gemm<1><<<dim3(DFF / 128, NQ / 128), 512, GSMEM_TOTAL>>>(
        NQ, DFF, 256, x16, w1, b_fc1, nullptr, h16);
    // proj = h @ W_fc2 + b_fc2
    hmma_gemm<0><<<dim3(2, NQ / 128), 512, GSMEM_TOTAL>>>(
        NQ, 256, DFF, h16, w2, b_fc2, proj_p, nullptr);
    // out = LN(x + proj)
    add_ln_kernel<false><<<NQ / 8, 256>>>(x_p, proj_p, ln2g, ln2b, out, nullptr);
}